// round 3
// baseline (speedup 1.0000x reference)
#include <cuda_runtime.h>

#define DDIM 10
#define NPAIR 55
#define TPB 256
#define GRID 2048
#define HID 16

// Deterministic two-stage reduction scratch (no atomics, no allocation).
__device__ float g_part[NPAIR][GRID];

// ---------------------------------------------------------------------------
// Kernel 1: Gram partials. Coalesced float4 loads staged through smem; each
// thread owns one row per tile and accumulates 55 upper-tri products.
// ---------------------------------------------------------------------------
__global__ void gram_kernel(const float* __restrict__ x, long long nrows) {
    __shared__ float sx[TPB * DDIM];
    __shared__ float swarp[TPB / 32][NPAIR];

    float acc[NPAIR];
#pragma unroll
    for (int k = 0; k < NPAIR; k++) acc[k] = 0.f;

    const long long ntiles = (nrows + TPB - 1) / TPB;
    const long long totalf = nrows * (long long)DDIM;

    for (long long t = blockIdx.x; t < ntiles; t += (long long)gridDim.x) {
        long long base = t * (long long)(TPB * DDIM);
        const float4* xv = reinterpret_cast<const float4*>(x + base);
        for (int i = threadIdx.x; i < TPB * DDIM / 4; i += TPB) {
            long long f0 = base + (long long)i * 4;
            float4 v;
            if (f0 + 3 < totalf) {
                v = __ldg(xv + i);
            } else {
                v.x = (f0 + 0 < totalf) ? x[f0 + 0] : 0.f;
                v.y = (f0 + 1 < totalf) ? x[f0 + 1] : 0.f;
                v.z = (f0 + 2 < totalf) ? x[f0 + 2] : 0.f;
                v.w = (f0 + 3 < totalf) ? x[f0 + 3] : 0.f;
            }
            reinterpret_cast<float4*>(sx)[i] = v;
        }
        __syncthreads();

        float r[DDIM];
        long long row = t * (long long)TPB + threadIdx.x;
        if (row < nrows) {
#pragma unroll
            for (int j = 0; j < DDIM; j++) r[j] = sx[threadIdx.x * DDIM + j];
        } else {
#pragma unroll
            for (int j = 0; j < DDIM; j++) r[j] = 0.f;
        }
        int k = 0;
#pragma unroll
        for (int i = 0; i < DDIM; i++)
#pragma unroll
            for (int j = i; j < DDIM; j++) acc[k++] += r[i] * r[j];
        __syncthreads();
    }

    // warp reduce each accumulator
#pragma unroll
    for (int k = 0; k < NPAIR; k++) {
#pragma unroll
        for (int off = 16; off > 0; off >>= 1)
            acc[k] += __shfl_down_sync(0xffffffffu, acc[k], off);
    }
    int wid = threadIdx.x >> 5, lane = threadIdx.x & 31;
    if (lane == 0) {
#pragma unroll
        for (int k = 0; k < NPAIR; k++) swarp[wid][k] = acc[k];
    }
    __syncthreads();
    if (threadIdx.x < NPAIR) {
        float s = 0.f;
#pragma unroll
        for (int w = 0; w < TPB / 32; w++) s += swarp[w][threadIdx.x];
        g_part[threadIdx.x][blockIdx.x] = s;
    }
}

// ---------------------------------------------------------------------------
// LAPACK-faithful float helpers (sign conventions matter for eigh matching)
// ---------------------------------------------------------------------------
__device__ __forceinline__ float lapy2f(float x, float y) {
    float ax = fabsf(x), ay = fabsf(y);
    float w = fmaxf(ax, ay), z = fminf(ax, ay);
    if (z == 0.f) return w;
    float t = z / w;
    return w * sqrtf(1.f + t * t);
}
__device__ __forceinline__ float signf(float a, float b) {
    return (b >= 0.f) ? fabsf(a) : -fabsf(a);
}
// LAPACK >= 3.10 slartg convention (c >= 0 always, r = sign(d, f))
__device__ __forceinline__ void lartgf(float f, float g, float& c, float& s, float& r) {
    if (g == 0.f) { c = 1.f; s = 0.f; r = f; }
    else if (f == 0.f) { c = 0.f; s = (g > 0.f) ? 1.f : -1.f; r = fabsf(g); }
    else {
        float d = sqrtf(f * f + g * g);
        c = fabsf(f) / d;
        r = signf(d, f);
        s = g / r;
    }
}
// LAPACK slaev2 (2x2 symmetric eigenproblem with its exact sign logic)
__device__ void laev2f(float a, float b, float c_, float& rt1, float& rt2,
                       float& cs1, float& sn1) {
    float sm = a + c_;
    float df = a - c_;
    float adf = fabsf(df);
    float tb = b + b;
    float ab = fabsf(tb);
    float acmx, acmn;
    if (fabsf(a) > fabsf(c_)) { acmx = a; acmn = c_; } else { acmx = c_; acmn = a; }
    float rt;
    if (adf > ab)      { float q = ab / adf; rt = adf * sqrtf(1.f + q * q); }
    else if (adf < ab) { float q = adf / ab; rt = ab * sqrtf(1.f + q * q); }
    else               { rt = ab * sqrtf(2.f); }
    int sgn1;
    if (sm < 0.f) {
        rt1 = 0.5f * (sm - rt); sgn1 = -1;
        rt2 = (acmx / rt1) * acmn - (b / rt1) * b;
    } else if (sm > 0.f) {
        rt1 = 0.5f * (sm + rt); sgn1 = 1;
        rt2 = (acmx / rt1) * acmn - (b / rt1) * b;
    } else {
        rt1 = 0.5f * rt; rt2 = -0.5f * rt; sgn1 = 1;
    }
    float cs; int sgn2;
    if (df >= 0.f) { cs = df + rt; sgn2 = 1; }
    else           { cs = df - rt; sgn2 = -1; }
    float acs = fabsf(cs);
    if (acs > ab) {
        float ct = -tb / cs;
        sn1 = 1.f / sqrtf(1.f + ct * ct);
        cs1 = ct * sn1;
    } else {
        if (ab == 0.f) { cs1 = 1.f; sn1 = 0.f; }
        else {
            float tn = -cs / tb;
            cs1 = 1.f / sqrtf(1.f + tn * tn);
            sn1 = tn * cs1;
        }
    }
    if (sgn1 == sgn2) { float tn = cs1; cs1 = -sn1; sn1 = tn; }
}

// ---------------------------------------------------------------------------
// Kernel 2: reduce partials -> gram; ssytd2 + ssteqr + sormtr (ssyevd path,
// lower triangle, eigenvalues ascending); then MLP + sigmoid.
// ---------------------------------------------------------------------------
__global__ void solve_kernel(const float* __restrict__ W1, const float* __restrict__ b1,
                             const float* __restrict__ W2, const float* __restrict__ b2,
                             float* __restrict__ out) {
    __shared__ float gram[NPAIR];
    __shared__ float Am[DDIM][DDIM];
    __shared__ float Zm[DDIM][DDIM];
    __shared__ float dd[DDIM], ee[DDIM], tauv[DDIM], wcs[DDIM], wss[DDIM], pv[DDIM];

    int wid = threadIdx.x >> 5, lane = threadIdx.x & 31;
    for (int k = wid; k < NPAIR; k += TPB / 32) {
        float s = 0.f;
        for (int i = lane; i < GRID; i += 32) s += g_part[k][i];
#pragma unroll
        for (int off = 16; off > 0; off >>= 1)
            s += __shfl_down_sync(0xffffffffu, s, off);
        if (lane == 0) gram[k] = s;
    }
    __syncthreads();
    if (threadIdx.x != 0) return;

    const int n = DDIM;
    {
        int k = 0;
        for (int i = 0; i < n; i++)
            for (int j = i; j < n; j++) { Am[i][j] = gram[k]; Am[j][i] = gram[k]; k++; }
    }

    // ---------------- ssytd2 (uplo='L') ----------------
    for (int i = 0; i < n - 1; i++) {
        float alpha = Am[i + 1][i];
        float xnorm = 0.f;
        for (int r = i + 2; r < n; r++) xnorm += Am[r][i] * Am[r][i];
        xnorm = sqrtf(xnorm);
        float taui;
        if (xnorm == 0.f) {
            taui = 0.f;
        } else {
            float beta = -signf(lapy2f(alpha, xnorm), alpha);
            taui = (beta - alpha) / beta;
            float sc = 1.f / (alpha - beta);
            for (int r = i + 2; r < n; r++) Am[r][i] *= sc;
            Am[i + 1][i] = beta;
        }
        ee[i] = Am[i + 1][i];
        if (taui != 0.f) {
            // p = taui * A(i+1:,i+1:) * v ; v[i+1]=1, v[r]=Am[r][i]
            for (int r = i + 1; r < n; r++) {
                float s = Am[r][i + 1];
                for (int c = i + 2; c < n; c++) s += Am[r][c] * Am[c][i];
                pv[r] = taui * s;
            }
            float vtp = pv[i + 1];
            for (int r = i + 2; r < n; r++) vtp += pv[r] * Am[r][i];
            float alph = -0.5f * taui * vtp;
            pv[i + 1] += alph;
            for (int r = i + 2; r < n; r++) pv[r] += alph * Am[r][i];
            // rank-2 update, maintain full symmetric storage
            for (int r = i + 1; r < n; r++) {
                float vr = (r == i + 1) ? 1.f : Am[r][i];
                float wr = pv[r];
                for (int c = i + 1; c < n; c++) {
                    float vc = (c == i + 1) ? 1.f : Am[c][i];
                    Am[r][c] -= vr * pv[c] + wr * vc;
                }
            }
        }
        dd[i] = Am[i][i];
        tauv[i] = taui;
    }
    dd[n - 1] = Am[n - 1][n - 1];

    // Z = I
    for (int r = 0; r < n; r++)
        for (int c = 0; c < n; c++) Zm[r][c] = (r == c) ? 1.f : 0.f;

    // ---------------- ssteqr (compz='I') ----------------
    {
        const float eps = 5.9604645e-8f;   // slamch('E')
        const float eps2 = eps * eps;
        const float safmin = 1.17549435e-38f;
        const int nmaxit = n * 30;
        int jtot = 0;
        int l1 = 1;
#define Dv(i) dd[(i) - 1]
#define Ev(i) ee[(i) - 1]
        while (l1 <= n) {
            if (l1 > 1) Ev(l1 - 1) = 0.f;
            int m = n;
            if (l1 <= n - 1) {
                for (int mm = l1; mm <= n - 1; mm++) {
                    float tst = fabsf(Ev(mm));
                    if (tst == 0.f) { m = mm; break; }
                    if (tst <= sqrtf(fabsf(Dv(mm))) * sqrtf(fabsf(Dv(mm + 1))) * eps) {
                        Ev(mm) = 0.f; m = mm; break;
                    }
                }
            }
            int l = l1, lend = m;
            l1 = m + 1;
            if (lend == l) continue;
            float anorm = 0.f;
            for (int i = l; i <= lend; i++) anorm = fmaxf(anorm, fabsf(Dv(i)));
            for (int i = l; i <= lend - 1; i++) anorm = fmaxf(anorm, fabsf(Ev(i)));
            if (anorm == 0.f) continue;
            if (fabsf(Dv(lend)) < fabsf(Dv(l))) { int t = l; l = lend; lend = t; }

            if (lend > l) {
                // ---- QL iteration ----
                while (true) {
                    int m2 = lend;
                    if (l != lend) {
                        for (int mm = l; mm <= lend - 1; mm++) {
                            float tst = fabsf(Ev(mm)); tst = tst * tst;
                            if (tst <= (eps2 * fabsf(Dv(mm))) * fabsf(Dv(mm + 1)) + safmin) { m2 = mm; break; }
                        }
                    }
                    if (m2 < lend) Ev(m2) = 0.f;
                    float p = Dv(l);
                    if (m2 == l) {
                        Dv(l) = p; l++;
                        if (l <= lend) continue;
                        break;
                    }
                    if (m2 == l + 1) {
                        float rt1, rt2, cc, ss;
                        laev2f(Dv(l), Ev(l), Dv(l + 1), rt1, rt2, cc, ss);
                        for (int rr = 0; rr < n; rr++) {           // rotate cols (l-1,l) 0-based
                            float t1 = Zm[rr][l];
                            float t0 = Zm[rr][l - 1];
                            Zm[rr][l] = cc * t1 - ss * t0;
                            Zm[rr][l - 1] = ss * t1 + cc * t0;
                        }
                        Dv(l) = rt1; Dv(l + 1) = rt2; Ev(l) = 0.f;
                        l += 2;
                        if (l <= lend) continue;
                        break;
                    }
                    if (jtot == nmaxit) break;
                    jtot++;
                    float g = (Dv(l + 1) - p) / (2.f * Ev(l));
                    float r = lapy2f(g, 1.f);
                    g = Dv(m2) - p + Ev(l) / (g + signf(r, g));
                    float s = 1.f, c = 1.f; p = 0.f;
                    for (int i = m2 - 1; i >= l; i--) {
                        float f = s * Ev(i), b = c * Ev(i);
                        lartgf(g, f, c, s, r);
                        if (i != m2 - 1) Ev(i + 1) = r;
                        g = Dv(i + 1) - p;
                        r = (Dv(i) - g) * s + 2.f * c * b;
                        p = s * r;
                        Dv(i + 1) = g + p;
                        g = c * r - b;
                        wcs[i - 1] = c;
                        wss[i - 1] = -s;                            // LAPACK stores -s for QL
                    }
                    // slasr 'R','V','B' on cols l..m2 (1-based)
                    for (int j = m2 - l; j >= 1; j--) {
                        float ct = wcs[(l - 1) + (j - 1)], st = wss[(l - 1) + (j - 1)];
                        if (ct != 1.f || st != 0.f) {
                            int c1 = (l - 1) + j, c0 = c1 - 1;
                            for (int rr = 0; rr < n; rr++) {
                                float temp = Zm[rr][c1];
                                Zm[rr][c1] = ct * temp - st * Zm[rr][c0];
                                Zm[rr][c0] = st * temp + ct * Zm[rr][c0];
                            }
                        }
                    }
                    Dv(l) -= p;
                    Ev(l) = g;
                }
            } else {
                // ---- QR iteration ----
                while (true) {
                    int m2 = lend;
                    if (l != lend) {
                        for (int mm = l; mm >= lend + 1; mm--) {
                            float tst = fabsf(Ev(mm - 1)); tst = tst * tst;
                            if (tst <= (eps2 * fabsf(Dv(mm))) * fabsf(Dv(mm - 1)) + safmin) { m2 = mm; break; }
                        }
                    }
                    if (m2 > lend) Ev(m2 - 1) = 0.f;
                    float p = Dv(l);
                    if (m2 == l) {
                        Dv(l) = p; l--;
                        if (l >= lend) continue;
                        break;
                    }
                    if (m2 == l - 1) {
                        float rt1, rt2, cc, ss;
                        laev2f(Dv(l - 1), Ev(l - 1), Dv(l), rt1, rt2, cc, ss);
                        for (int rr = 0; rr < n; rr++) {           // rotate cols (l-2,l-1) 0-based
                            float t1 = Zm[rr][l - 1];
                            float t0 = Zm[rr][l - 2];
                            Zm[rr][l - 1] = cc * t1 - ss * t0;
                            Zm[rr][l - 2] = ss * t1 + cc * t0;
                        }
                        Dv(l - 1) = rt1; Dv(l) = rt2; Ev(l - 1) = 0.f;
                        l -= 2;
                        if (l >= lend) continue;
                        break;
                    }
                    if (jtot == nmaxit) break;
                    jtot++;
                    float g = (Dv(l - 1) - p) / (2.f * Ev(l - 1));
                    float r = lapy2f(g, 1.f);
                    g = Dv(m2) - p + Ev(l - 1) / (g + signf(r, g));
                    float s = 1.f, c = 1.f; p = 0.f;
                    for (int i = m2; i <= l - 1; i++) {
                        float f = s * Ev(i), b = c * Ev(i);
                        lartgf(g, f, c, s, r);
                        if (i != m2) Ev(i - 1) = r;
                        g = Dv(i) - p;
                        r = (Dv(i + 1) - g) * s + 2.f * c * b;
                        p = s * r;
                        Dv(i) = g + p;
                        g = c * r - b;
                        wcs[i - 1] = c;
                        wss[i - 1] = s;
                    }
                    // slasr 'R','V','F' on cols m2..l (1-based)
                    for (int j = 1; j <= l - m2; j++) {
                        float ct = wcs[(m2 - 1) + (j - 1)], st = wss[(m2 - 1) + (j - 1)];
                        if (ct != 1.f || st != 0.f) {
                            int c1 = (m2 - 1) + j, c0 = c1 - 1;
                            for (int rr = 0; rr < n; rr++) {
                                float temp = Zm[rr][c1];
                                Zm[rr][c1] = ct * temp - st * Zm[rr][c0];
                                Zm[rr][c0] = st * temp + ct * Zm[rr][c0];
                            }
                        }
                    }
                    Dv(l) -= p;
                    Ev(l - 1) = g;
                }
            }
        }
        // selection sort ascending + column swaps (LAPACK dsteqr label 160)
        for (int ii = 2; ii <= n; ii++) {
            int i = ii - 1, k = i;
            float p = Dv(i);
            for (int j = ii; j <= n; j++)
                if (Dv(j) < p) { k = j; p = Dv(j); }
            if (k != i) {
                Dv(k) = Dv(i); Dv(i) = p;
                for (int rr = 0; rr < n; rr++) {
                    float t = Zm[rr][i - 1]; Zm[rr][i - 1] = Zm[rr][k - 1]; Zm[rr][k - 1] = t;
                }
            }
        }
#undef Dv
#undef Ev
    }

    // ---------------- sormtr: Z := H(1)...H(n-1) Z  (apply i = n-2..0) ----
    for (int i = n - 2; i >= 0; i--) {
        if (tauv[i] == 0.f) continue;
        for (int c = 0; c < n; c++) {
            float s = Zm[i + 1][c];
            for (int r = i + 2; r < n; r++) s += Am[r][i] * Zm[r][c];
            s *= tauv[i];
            Zm[i + 1][c] -= s;
            for (int r = i + 2; r < n; r++) Zm[r][c] -= s * Am[r][i];
        }
    }

    // ---------------- MLP: relu(w @ W1^T + b1) @ W2^T + b2; 0.5*(sigmoid+1)
    for (int r = 0; r < n; r++) {
        float y2 = b2[0];
        for (int h = 0; h < HID; h++) {
            float a = b1[h];
            for (int k = 0; k < DDIM; k++) a += Zm[r][k] * W1[h * DDIM + k];
            a = fmaxf(a, 0.f);
            y2 += a * W2[h];
        }
        out[r] = 0.5f * (1.f / (1.f + expf(-y2)) + 1.f);
    }
}

// ---------------------------------------------------------------------------
extern "C" void kernel_launch(void* const* d_in, const int* in_sizes, int n_in,
                              void* d_out, int out_size) {
    const float* x  = (const float*)d_in[0];
    const float* W1 = (const float*)d_in[1];
    const float* b1 = (const float*)d_in[2];
    const float* W2 = (const float*)d_in[3];
    const float* b2 = (const float*)d_in[4];
    long long nrows = (long long)in_sizes[0] / DDIM;

    gram_kernel<<<GRID, TPB>>>(x, nrows);
    solve_kernel<<<1, TPB>>>(W1, b1, W2, b2, (float*)d_out);
}

// round 4
// speedup vs baseline: 1.8754x; 1.8754x over previous
#include <cuda_runtime.h>

#define DDIM 10
#define NPAIR 55
#define GTPB 256
#define GGRID 1184
#define RTPB 256
#define HID 16

// Deterministic two-stage reduction scratch (no atomics, no allocation).
__device__ float g_part[NPAIR][GGRID];
__device__ float g_gram[NPAIR];

// ---------------------------------------------------------------------------
// Kernel 1: Gram partials. Direct per-row float2 loads (no smem staging, no
// syncthreads) so LDGs and the 55-FMA chains pipeline freely.
// ---------------------------------------------------------------------------
__global__ void __launch_bounds__(GTPB, 2)
gram_kernel(const float* __restrict__ x, long long nrows) {
    __shared__ float swarp[GTPB / 32][NPAIR];

    float acc[NPAIR];
#pragma unroll
    for (int k = 0; k < NPAIR; k++) acc[k] = 0.f;

    long long tid = (long long)blockIdx.x * GTPB + threadIdx.x;
    const long long stride = (long long)GGRID * GTPB;

    for (long long row = tid; row < nrows; row += stride) {
        const float2* xr = reinterpret_cast<const float2*>(x + row * (long long)DDIM);
        float r[DDIM];
#pragma unroll
        for (int j = 0; j < 5; j++) {
            float2 v = __ldg(xr + j);
            r[2 * j] = v.x;
            r[2 * j + 1] = v.y;
        }
        int k = 0;
#pragma unroll
        for (int i = 0; i < DDIM; i++)
#pragma unroll
            for (int j = i; j < DDIM; j++) acc[k++] += r[i] * r[j];
    }

    // warp reduce each accumulator
#pragma unroll
    for (int k = 0; k < NPAIR; k++) {
#pragma unroll
        for (int off = 16; off > 0; off >>= 1)
            acc[k] += __shfl_down_sync(0xffffffffu, acc[k], off);
    }
    int wid = threadIdx.x >> 5, lane = threadIdx.x & 31;
    if (lane == 0) {
#pragma unroll
        for (int k = 0; k < NPAIR; k++) swarp[wid][k] = acc[k];
    }
    __syncthreads();
    if (threadIdx.x < NPAIR) {
        float s = 0.f;
#pragma unroll
        for (int w = 0; w < GTPB / 32; w++) s += swarp[w][threadIdx.x];
        g_part[threadIdx.x][blockIdx.x] = s;
    }
}

// ---------------------------------------------------------------------------
// Kernel 2: parallel reduction of partials -> g_gram[55]. One block per pair,
// deterministic fixed-shape tree.
// ---------------------------------------------------------------------------
__global__ void reduce_kernel() {
    __shared__ float sm[RTPB];
    int k = blockIdx.x;
    float s = 0.f;
    for (int i = threadIdx.x; i < GGRID; i += RTPB) s += g_part[k][i];
    sm[threadIdx.x] = s;
    __syncthreads();
    for (int off = RTPB / 2; off > 0; off >>= 1) {
        if (threadIdx.x < off) sm[threadIdx.x] += sm[threadIdx.x + off];
        __syncthreads();
    }
    if (threadIdx.x == 0) g_gram[k] = sm[0];
}

// ---------------------------------------------------------------------------
// LAPACK-faithful float helpers (sign conventions matter for eigh matching)
// ---------------------------------------------------------------------------
__device__ __forceinline__ float lapy2f(float x, float y) {
    float ax = fabsf(x), ay = fabsf(y);
    float w = fmaxf(ax, ay), z = fminf(ax, ay);
    if (z == 0.f) return w;
    float t = z / w;
    return w * sqrtf(1.f + t * t);
}
__device__ __forceinline__ float signf(float a, float b) {
    return (b >= 0.f) ? fabsf(a) : -fabsf(a);
}
// LAPACK >= 3.10 slartg convention (c >= 0 always, r = sign(d, f))
__device__ __forceinline__ void lartgf(float f, float g, float& c, float& s, float& r) {
    if (g == 0.f) { c = 1.f; s = 0.f; r = f; }
    else if (f == 0.f) { c = 0.f; s = (g > 0.f) ? 1.f : -1.f; r = fabsf(g); }
    else {
        float d = sqrtf(f * f + g * g);
        c = fabsf(f) / d;
        r = signf(d, f);
        s = g / r;
    }
}
// LAPACK slaev2 (2x2 symmetric eigenproblem with its exact sign logic)
__device__ void laev2f(float a, float b, float c_, float& rt1, float& rt2,
                       float& cs1, float& sn1) {
    float sm = a + c_;
    float df = a - c_;
    float adf = fabsf(df);
    float tb = b + b;
    float ab = fabsf(tb);
    float acmx, acmn;
    if (fabsf(a) > fabsf(c_)) { acmx = a; acmn = c_; } else { acmx = c_; acmn = a; }
    float rt;
    if (adf > ab)      { float q = ab / adf; rt = adf * sqrtf(1.f + q * q); }
    else if (adf < ab) { float q = adf / ab; rt = ab * sqrtf(1.f + q * q); }
    else               { rt = ab * sqrtf(2.f); }
    int sgn1;
    if (sm < 0.f) {
        rt1 = 0.5f * (sm - rt); sgn1 = -1;
        rt2 = (acmx / rt1) * acmn - (b / rt1) * b;
    } else if (sm > 0.f) {
        rt1 = 0.5f * (sm + rt); sgn1 = 1;
        rt2 = (acmx / rt1) * acmn - (b / rt1) * b;
    } else {
        rt1 = 0.5f * rt; rt2 = -0.5f * rt; sgn1 = 1;
    }
    float cs; int sgn2;
    if (df >= 0.f) { cs = df + rt; sgn2 = 1; }
    else           { cs = df - rt; sgn2 = -1; }
    float acs = fabsf(cs);
    if (acs > ab) {
        float ct = -tb / cs;
        sn1 = 1.f / sqrtf(1.f + ct * ct);
        cs1 = ct * sn1;
    } else {
        if (ab == 0.f) { cs1 = 1.f; sn1 = 0.f; }
        else {
            float tn = -cs / tb;
            cs1 = 1.f / sqrtf(1.f + tn * tn);
            sn1 = tn * cs1;
        }
    }
    if (sgn1 == sgn2) { float tn = cs1; cs1 = -sn1; sn1 = tn; }
}

// ---------------------------------------------------------------------------
// Kernel 3: warp-parallel ssytd2 + ssteqr + sormtr + MLP.
// All 32 lanes redundantly execute the scalar LAPACK chain (identical
// arithmetic -> identical signs); O(n) row/column loops are lane-distributed.
// Zm is row-owned by lane rr throughout steqr/sort, column-owned in sormtr.
// ---------------------------------------------------------------------------
__global__ void solve_kernel(const float* __restrict__ W1, const float* __restrict__ b1,
                             const float* __restrict__ W2, const float* __restrict__ b2,
                             float* __restrict__ out) {
    __shared__ float Am[DDIM][DDIM];
    __shared__ float Zm[DDIM][DDIM];
    __shared__ float dd[DDIM], ee[DDIM], tauv[DDIM], wcs[DDIM], wss[DDIM], pv[DDIM];

    const int lane = threadIdx.x;
    const int n = DDIM;

    // scatter gram into full symmetric Am
    for (int k = lane; k < NPAIR; k += 32) {
        int i = 0, rem = k;
        while (rem >= n - i) { rem -= (n - i); i++; }
        int j = i + rem;
        float v = g_gram[k];
        Am[i][j] = v;
        Am[j][i] = v;
    }
    __syncwarp();

    // ---------------- ssytd2 (uplo='L') ----------------
    for (int i = 0; i < n - 1; i++) {
        float alpha = Am[i + 1][i];
        float xnorm = 0.f;
        for (int r = i + 2; r < n; r++) xnorm += Am[r][i] * Am[r][i];
        xnorm = sqrtf(xnorm);
        float taui = 0.f;
        if (xnorm != 0.f) {
            float beta = -signf(lapy2f(alpha, xnorm), alpha);
            taui = (beta - alpha) / beta;
            float sc = 1.f / (alpha - beta);
            if (lane >= i + 2 && lane < n) Am[lane][i] *= sc;
            if (lane == 0) Am[i + 1][i] = beta;
            __syncwarp();
        }
        ee[i] = Am[i + 1][i];
        if (taui != 0.f) {
            // pv[r] = taui * (A v)_r  (v[i+1]=1, v[r]=Am[r][i])
            if (lane >= i + 1 && lane < n) {
                int r = lane;
                float s = Am[r][i + 1];
                for (int c = i + 2; c < n; c++) s += Am[r][c] * Am[c][i];
                pv[r] = taui * s;
            }
            __syncwarp();
            float vtp = pv[i + 1];
            for (int r = i + 2; r < n; r++) vtp += pv[r] * Am[r][i];
            float alph = -0.5f * taui * vtp;
            __syncwarp();
            if (lane >= i + 1 && lane < n) {
                if (lane == i + 1) pv[lane] += alph;
                else               pv[lane] += alph * Am[lane][i];
            }
            __syncwarp();
            // rank-2 update: lane r owns row r
            if (lane >= i + 1 && lane < n) {
                int r = lane;
                float vr = (r == i + 1) ? 1.f : Am[r][i];
                float wr = pv[r];
                for (int c = i + 1; c < n; c++) {
                    float vc = (c == i + 1) ? 1.f : Am[c][i];
                    Am[r][c] -= vr * pv[c] + wr * vc;
                }
            }
            __syncwarp();
        }
        dd[i] = Am[i][i];
        tauv[i] = taui;
        __syncwarp();
    }
    dd[n - 1] = Am[n - 1][n - 1];

    // Z = I (row-owned)
    if (lane < n)
        for (int c = 0; c < n; c++) Zm[lane][c] = (lane == c) ? 1.f : 0.f;
    __syncwarp();

    // ---------------- ssteqr (compz='I'); Zm stays row-owned ----------------
    {
        const float eps = 5.9604645e-8f;   // slamch('E')
        const float eps2 = eps * eps;
        const float safmin = 1.17549435e-38f;
        const int nmaxit = n * 30;
        int jtot = 0;
        int l1 = 1;
#define Dv(i) dd[(i) - 1]
#define Ev(i) ee[(i) - 1]
        while (l1 <= n) {
            if (l1 > 1) Ev(l1 - 1) = 0.f;
            int m = n;
            if (l1 <= n - 1) {
                for (int mm = l1; mm <= n - 1; mm++) {
                    float tst = fabsf(Ev(mm));
                    if (tst == 0.f) { m = mm; break; }
                    if (tst <= sqrtf(fabsf(Dv(mm))) * sqrtf(fabsf(Dv(mm + 1))) * eps) {
                        Ev(mm) = 0.f; m = mm; break;
                    }
                }
            }
            int l = l1, lend = m;
            l1 = m + 1;
            if (lend == l) continue;
            float anorm = 0.f;
            for (int i = l; i <= lend; i++) anorm = fmaxf(anorm, fabsf(Dv(i)));
            for (int i = l; i <= lend - 1; i++) anorm = fmaxf(anorm, fabsf(Ev(i)));
            if (anorm == 0.f) continue;
            if (fabsf(Dv(lend)) < fabsf(Dv(l))) { int t = l; l = lend; lend = t; }

            if (lend > l) {
                // ---- QL iteration ----
                while (true) {
                    int m2 = lend;
                    if (l != lend) {
                        for (int mm = l; mm <= lend - 1; mm++) {
                            float tst = fabsf(Ev(mm)); tst = tst * tst;
                            if (tst <= (eps2 * fabsf(Dv(mm))) * fabsf(Dv(mm + 1)) + safmin) { m2 = mm; break; }
                        }
                    }
                    if (m2 < lend) Ev(m2) = 0.f;
                    float p = Dv(l);
                    if (m2 == l) {
                        Dv(l) = p; l++;
                        if (l <= lend) continue;
                        break;
                    }
                    if (m2 == l + 1) {
                        float rt1, rt2, cc, ss;
                        laev2f(Dv(l), Ev(l), Dv(l + 1), rt1, rt2, cc, ss);
                        if (lane < n) {                          // rotate cols (l-1,l) 0-based
                            float t1 = Zm[lane][l];
                            float t0 = Zm[lane][l - 1];
                            Zm[lane][l] = cc * t1 - ss * t0;
                            Zm[lane][l - 1] = ss * t1 + cc * t0;
                        }
                        Dv(l) = rt1; Dv(l + 1) = rt2; Ev(l) = 0.f;
                        l += 2;
                        if (l <= lend) continue;
                        break;
                    }
                    if (jtot == nmaxit) break;
                    jtot++;
                    float g = (Dv(l + 1) - p) / (2.f * Ev(l));
                    float r = lapy2f(g, 1.f);
                    g = Dv(m2) - p + Ev(l) / (g + signf(r, g));
                    float s = 1.f, c = 1.f; p = 0.f;
                    for (int i = m2 - 1; i >= l; i--) {
                        float f = s * Ev(i), b = c * Ev(i);
                        lartgf(g, f, c, s, r);
                        if (i != m2 - 1) Ev(i + 1) = r;
                        g = Dv(i + 1) - p;
                        r = (Dv(i) - g) * s + 2.f * c * b;
                        p = s * r;
                        Dv(i + 1) = g + p;
                        g = c * r - b;
                        wcs[i - 1] = c;
                        wss[i - 1] = -s;                         // LAPACK stores -s for QL
                    }
                    // slasr 'R','V','B' on cols l..m2 (1-based); lane owns row
                    if (lane < n) {
                        for (int j = m2 - l; j >= 1; j--) {
                            float ct = wcs[(l - 1) + (j - 1)], st = wss[(l - 1) + (j - 1)];
                            if (ct != 1.f || st != 0.f) {
                                int c1 = (l - 1) + j, c0 = c1 - 1;
                                float temp = Zm[lane][c1];
                                Zm[lane][c1] = ct * temp - st * Zm[lane][c0];
                                Zm[lane][c0] = st * temp + ct * Zm[lane][c0];
                            }
                        }
                    }
                    Dv(l) -= p;
                    Ev(l) = g;
                }
            } else {
                // ---- QR iteration ----
                while (true) {
                    int m2 = lend;
                    if (l != lend) {
                        for (int mm = l; mm >= lend + 1; mm--) {
                            float tst = fabsf(Ev(mm - 1)); tst = tst * tst;
                            if (tst <= (eps2 * fabsf(Dv(mm))) * fabsf(Dv(mm - 1)) + safmin) { m2 = mm; break; }
                        }
                    }
                    if (m2 > lend) Ev(m2 - 1) = 0.f;
                    float p = Dv(l);
                    if (m2 == l) {
                        Dv(l) = p; l--;
                        if (l >= lend) continue;
                        break;
                    }
                    if (m2 == l - 1) {
                        float rt1, rt2, cc, ss;
                        laev2f(Dv(l - 1), Ev(l - 1), Dv(l), rt1, rt2, cc, ss);
                        if (lane < n) {                          // rotate cols (l-2,l-1) 0-based
                            float t1 = Zm[lane][l - 1];
                            float t0 = Zm[lane][l - 2];
                            Zm[lane][l - 1] = cc * t1 - ss * t0;
                            Zm[lane][l - 2] = ss * t1 + cc * t0;
                        }
                        Dv(l - 1) = rt1; Dv(l) = rt2; Ev(l - 1) = 0.f;
                        l -= 2;
                        if (l >= lend) continue;
                        break;
                    }
                    if (jtot == nmaxit) break;
                    jtot++;
                    float g = (Dv(l - 1) - p) / (2.f * Ev(l - 1));
                    float r = lapy2f(g, 1.f);
                    g = Dv(m2) - p + Ev(l - 1) / (g + signf(r, g));
                    float s = 1.f, c = 1.f; p = 0.f;
                    for (int i = m2; i <= l - 1; i++) {
                        float f = s * Ev(i), b = c * Ev(i);
                        lartgf(g, f, c, s, r);
                        if (i != m2) Ev(i - 1) = r;
                        g = Dv(i) - p;
                        r = (Dv(i + 1) - g) * s + 2.f * c * b;
                        p = s * r;
                        Dv(i) = g + p;
                        g = c * r - b;
                        wcs[i - 1] = c;
                        wss[i - 1] = s;
                    }
                    // slasr 'R','V','F' on cols m2..l (1-based); lane owns row
                    if (lane < n) {
                        for (int j = 1; j <= l - m2; j++) {
                            float ct = wcs[(m2 - 1) + (j - 1)], st = wss[(m2 - 1) + (j - 1)];
                            if (ct != 1.f || st != 0.f) {
                                int c1 = (m2 - 1) + j, c0 = c1 - 1;
                                float temp = Zm[lane][c1];
                                Zm[lane][c1] = ct * temp - st * Zm[lane][c0];
                                Zm[lane][c0] = st * temp + ct * Zm[lane][c0];
                            }
                        }
                    }
                    Dv(l) -= p;
                    Ev(l - 1) = g;
                }
            }
        }
        // selection sort ascending + column swaps (lane owns row)
        for (int ii = 2; ii <= n; ii++) {
            int i = ii - 1, k = i;
            float p = Dv(i);
            for (int j = ii; j <= n; j++)
                if (Dv(j) < p) { k = j; p = Dv(j); }
            if (k != i) {
                Dv(k) = Dv(i); Dv(i) = p;
                if (lane < n) {
                    float t = Zm[lane][i - 1];
                    Zm[lane][i - 1] = Zm[lane][k - 1];
                    Zm[lane][k - 1] = t;
                }
            }
        }
#undef Dv
#undef Ev
    }
    __syncwarp();   // Zm switches from row-owned to column-owned

    // ---------------- sormtr: Z := H(1)...H(n-1) Z ; lane owns column ----
    for (int i = n - 2; i >= 0; i--) {
        if (tauv[i] == 0.f) continue;
        if (lane < n) {
            int c = lane;
            float s = Zm[i + 1][c];
            for (int r = i + 2; r < n; r++) s += Am[r][i] * Zm[r][c];
            s *= tauv[i];
            Zm[i + 1][c] -= s;
            for (int r = i + 2; r < n; r++) Zm[r][c] -= s * Am[r][i];
        }
    }
    __syncwarp();   // back to row reads for the MLP

    // ---------------- MLP: relu(w @ W1^T + b1) @ W2^T + b2; 0.5*(sigmoid+1)
    if (lane < n) {
        float zr[DDIM];
#pragma unroll
        for (int k = 0; k < DDIM; k++) zr[k] = Zm[lane][k];
        float y2 = b2[0];
        for (int h = 0; h < HID; h++) {
            float a = b1[h];
#pragma unroll
            for (int k = 0; k < DDIM; k++) a += zr[k] * W1[h * DDIM + k];
            a = fmaxf(a, 0.f);
            y2 += a * W2[h];
        }
        out[lane] = 0.5f * (1.f / (1.f + expf(-y2)) + 1.f);
    }
}

// ---------------------------------------------------------------------------
extern "C" void kernel_launch(void* const* d_in, const int* in_sizes, int n_in,
                              void* d_out, int out_size) {
    const float* x  = (const float*)d_in[0];
    const float* W1 = (const float*)d_in[1];
    const float* b1 = (const float*)d_in[2];
    const float* W2 = (const float*)d_in[3];
    const float* b2 = (const float*)d_in[4];
    long long nrows = (long long)in_sizes[0] / DDIM;

    gram_kernel<<<GGRID, GTPB>>>(x, nrows);
    reduce_kernel<<<NPAIR, RTPB>>>();
    solve_kernel<<<1, 32>>>(W1, b1, W2, b2, (float*)d_out);
}

// round 5
// speedup vs baseline: 2.3550x; 1.2557x over previous
#include <cuda_runtime.h>
#include <cstdint>

#define DDIM 10
#define NPAIR 55
#define GTPB 256
#define GGRID 296            // 148 SMs x 2 blocks -> one full wave
#define ROWS_TILE 512        // rows per tile (2 rows / thread)
#define TILE_F4 (ROWS_TILE * DDIM / 4)   // 1280 float4 per tile
#define TILE_FLOATS (ROWS_TILE * DDIM)   // 5120 floats per tile
#define HID 16

// Deterministic two-stage reduction scratch (no atomics, no allocation).
__device__ float g_part[NPAIR][GGRID];

// ---------------------------------------------------------------------------
// async-copy helpers
// ---------------------------------------------------------------------------
__device__ __forceinline__ void cp_async16(uint32_t smem_dst, const void* gsrc) {
    asm volatile("cp.async.cg.shared.global [%0], [%1], 16;\n"
                 :: "r"(smem_dst), "l"(gsrc));
}
__device__ __forceinline__ void cp_commit() {
    asm volatile("cp.async.commit_group;\n");
}
__device__ __forceinline__ void cp_wait0() {
    asm volatile("cp.async.wait_group 0;\n");
}
__device__ __forceinline__ void cp_wait1() {
    asm volatile("cp.async.wait_group 1;\n");
}

// ---------------------------------------------------------------------------
// Kernel 1: Gram partials. Double-buffered cp.async staging (coalesced
// LDGSTS.128) overlapping next-tile loads with current-tile FMA.
// ---------------------------------------------------------------------------
__global__ void __launch_bounds__(GTPB, 2)
gram_kernel(const float* __restrict__ x, long long nrows) {
    __shared__ __align__(16) float sbuf[2][TILE_FLOATS];
    __shared__ float swarp[GTPB / 32][NPAIR];

    float acc[NPAIR];
#pragma unroll
    for (int k = 0; k < NPAIR; k++) acc[k] = 0.f;

    const long long ntiles = (nrows + ROWS_TILE - 1) / ROWS_TILE;
    const long long totalf4 = nrows * (long long)DDIM / 4;
    const float4* xsrc = reinterpret_cast<const float4*>(x);
    const uint32_t sbase = (uint32_t)__cvta_generic_to_shared(&sbuf[0][0]);

    long long t = blockIdx.x;
    bool havecur = (t < ntiles);

    // prologue: stage tile t into buffer 0
    if (havecur) {
        long long base4 = t * (long long)TILE_F4;
#pragma unroll
        for (int j = 0; j < TILE_F4 / GTPB; j++) {
            int i = threadIdx.x + j * GTPB;
            long long g4 = base4 + i;
            if (g4 < totalf4) {
                cp_async16(sbase + (uint32_t)i * 16u, xsrc + g4);
            } else {
                float4 z = make_float4(0.f, 0.f, 0.f, 0.f);
                reinterpret_cast<float4*>(&sbuf[0][0])[i] = z;
            }
        }
        cp_commit();
    }

    int buf = 0;
    while (havecur) {
        long long tn = t + (long long)GGRID;
        bool havenext = (tn < ntiles);
        if (havenext) {
            long long base4 = tn * (long long)TILE_F4;
            uint32_t dbase = sbase + (uint32_t)(buf ^ 1) * (TILE_FLOATS * 4u);
#pragma unroll
            for (int j = 0; j < TILE_F4 / GTPB; j++) {
                int i = threadIdx.x + j * GTPB;
                long long g4 = base4 + i;
                if (g4 < totalf4) {
                    cp_async16(dbase + (uint32_t)i * 16u, xsrc + g4);
                } else {
                    float4 z = make_float4(0.f, 0.f, 0.f, 0.f);
                    reinterpret_cast<float4*>(&sbuf[buf ^ 1][0])[i] = z;
                }
            }
            cp_commit();
            cp_wait1();          // current tile's group done
        } else {
            cp_wait0();
        }
        __syncthreads();

        // compute: this thread owns rows tid and tid+256 of the tile
        const float* sb = &sbuf[buf][0];
#pragma unroll
        for (int half = 0; half < 2; half++) {
            int r0 = threadIdx.x + half * GTPB;
            long long row_g = t * (long long)ROWS_TILE + r0;
            if (row_g < nrows) {
                float r[DDIM];
                const float2* rp = reinterpret_cast<const float2*>(sb + r0 * DDIM);
#pragma unroll
                for (int j = 0; j < 5; j++) {
                    float2 v = rp[j];
                    r[2 * j] = v.x;
                    r[2 * j + 1] = v.y;
                }
                int k = 0;
#pragma unroll
                for (int i = 0; i < DDIM; i++)
#pragma unroll
                    for (int j = i; j < DDIM; j++) acc[k++] += r[i] * r[j];
            }
        }
        __syncthreads();         // compute done before buf gets overwritten

        t = tn;
        havecur = havenext;
        buf ^= 1;
    }

    // warp reduce each accumulator
#pragma unroll
    for (int k = 0; k < NPAIR; k++) {
#pragma unroll
        for (int off = 16; off > 0; off >>= 1)
            acc[k] += __shfl_down_sync(0xffffffffu, acc[k], off);
    }
    int wid = threadIdx.x >> 5, lane = threadIdx.x & 31;
    if (lane == 0) {
#pragma unroll
        for (int k = 0; k < NPAIR; k++) swarp[wid][k] = acc[k];
    }
    __syncthreads();
    if (threadIdx.x < NPAIR) {
        float s = 0.f;
#pragma unroll
        for (int w = 0; w < GTPB / 32; w++) s += swarp[w][threadIdx.x];
        g_part[threadIdx.x][blockIdx.x] = s;
    }
}

// ---------------------------------------------------------------------------
// Fast-approx scalar helpers (sign-safe; ~1e-7 rel err, budget is 1e-3)
// ---------------------------------------------------------------------------
__device__ __forceinline__ float fdivf(float a, float b) { return __fdividef(a, b); }
__device__ __forceinline__ float fsqrta(float x) {
    float r;
    asm("sqrt.approx.f32 %0, %1;" : "=f"(r) : "f"(x));
    return r;   // sqrt.approx(+0) = +0
}

// ---------------------------------------------------------------------------
// LAPACK-faithful helpers (sign conventions preserved; magnitudes approx)
// ---------------------------------------------------------------------------
__device__ __forceinline__ float lapy2f(float x, float y) {
    float ax = fabsf(x), ay = fabsf(y);
    float w = fmaxf(ax, ay), z = fminf(ax, ay);
    if (z == 0.f) return w;
    float t = fdivf(z, w);
    return w * fsqrta(1.f + t * t);
}
__device__ __forceinline__ float signf(float a, float b) {
    return (b >= 0.f) ? fabsf(a) : -fabsf(a);
}
// LAPACK >= 3.10 slartg convention (c >= 0 always, r = sign(d, f))
__device__ __forceinline__ void lartgf(float f, float g, float& c, float& s, float& r) {
    if (g == 0.f) { c = 1.f; s = 0.f; r = f; }
    else if (f == 0.f) { c = 0.f; s = (g > 0.f) ? 1.f : -1.f; r = fabsf(g); }
    else {
        float d = fsqrta(f * f + g * g);
        c = fdivf(fabsf(f), d);
        r = signf(d, f);
        s = fdivf(g, r);
    }
}
// LAPACK slaev2 (2x2 symmetric eigenproblem with its exact sign logic)
__device__ void laev2f(float a, float b, float c_, float& rt1, float& rt2,
                       float& cs1, float& sn1) {
    float sm = a + c_;
    float df = a - c_;
    float adf = fabsf(df);
    float tb = b + b;
    float ab = fabsf(tb);
    float acmx, acmn;
    if (fabsf(a) > fabsf(c_)) { acmx = a; acmn = c_; } else { acmx = c_; acmn = a; }
    float rt;
    if (adf > ab)      { float q = fdivf(ab, adf); rt = adf * fsqrta(1.f + q * q); }
    else if (adf < ab) { float q = fdivf(adf, ab); rt = ab * fsqrta(1.f + q * q); }
    else               { rt = ab * fsqrta(2.f); }
    int sgn1;
    if (sm < 0.f) {
        rt1 = 0.5f * (sm - rt); sgn1 = -1;
        rt2 = fdivf(acmx, rt1) * acmn - fdivf(b, rt1) * b;
    } else if (sm > 0.f) {
        rt1 = 0.5f * (sm + rt); sgn1 = 1;
        rt2 = fdivf(acmx, rt1) * acmn - fdivf(b, rt1) * b;
    } else {
        rt1 = 0.5f * rt; rt2 = -0.5f * rt; sgn1 = 1;
    }
    float cs; int sgn2;
    if (df >= 0.f) { cs = df + rt; sgn2 = 1; }
    else           { cs = df - rt; sgn2 = -1; }
    float acs = fabsf(cs);
    if (acs > ab) {
        float ct = -fdivf(tb, cs);
        sn1 = rsqrtf(1.f + ct * ct);
        cs1 = ct * sn1;
    } else {
        if (ab == 0.f) { cs1 = 1.f; sn1 = 0.f; }
        else {
            float tn = -fdivf(cs, tb);
            cs1 = rsqrtf(1.f + tn * tn);
            sn1 = tn * cs1;
        }
    }
    if (sgn1 == sgn2) { float tn = cs1; cs1 = -sn1; sn1 = tn; }
}

// ---------------------------------------------------------------------------
// Kernel 2: partial-reduce (8 warps) then warp-parallel ssytd2 + ssteqr +
// sormtr + MLP on warp 0. Lanes redundantly run the scalar LAPACK chain
// (identical arithmetic -> identical signs); O(n) loops lane-distributed.
// ---------------------------------------------------------------------------
__global__ void solve_kernel(const float* __restrict__ W1, const float* __restrict__ b1,
                             const float* __restrict__ W2, const float* __restrict__ b2,
                             float* __restrict__ out) {
    __shared__ float gram[NPAIR];
    __shared__ float Am[DDIM][DDIM];
    __shared__ float Zm[DDIM][DDIM];
    __shared__ float dd[DDIM], ee[DDIM], tauv[DDIM], wcs[DDIM], wss[DDIM], pv[DDIM];

    const int tid = threadIdx.x;
    const int wrp = tid >> 5;
    const int lane = tid & 31;
    const int n = DDIM;

    // ---- stage 1: tree-reduce partials (all 8 warps) ----
    for (int k = wrp; k < NPAIR; k += 8) {
        float s = 0.f;
        for (int i = lane; i < GGRID; i += 32) s += g_part[k][i];
#pragma unroll
        for (int off = 16; off > 0; off >>= 1)
            s += __shfl_down_sync(0xffffffffu, s, off);
        if (lane == 0) gram[k] = s;
    }
    __syncthreads();
    if (tid >= 32) return;

    // scatter gram into full symmetric Am
    for (int k = lane; k < NPAIR; k += 32) {
        int i = 0, rem = k;
        while (rem >= n - i) { rem -= (n - i); i++; }
        int j = i + rem;
        float v = gram[k];
        Am[i][j] = v;
        Am[j][i] = v;
    }
    __syncwarp();

    // ---------------- ssytd2 (uplo='L') ----------------
    for (int i = 0; i < n - 1; i++) {
        float alpha = Am[i + 1][i];
        float xnorm = 0.f;
        for (int r = i + 2; r < n; r++) xnorm += Am[r][i] * Am[r][i];
        xnorm = fsqrta(xnorm);
        float taui = 0.f;
        if (xnorm != 0.f) {
            float beta = -signf(lapy2f(alpha, xnorm), alpha);
            taui = fdivf(beta - alpha, beta);
            float sc = fdivf(1.f, alpha - beta);
            if (lane >= i + 2 && lane < n) Am[lane][i] *= sc;
            if (lane == 0) Am[i + 1][i] = beta;
            __syncwarp();
        }
        ee[i] = Am[i + 1][i];
        if (taui != 0.f) {
            // pv[r] = taui * (A v)_r  (v[i+1]=1, v[r]=Am[r][i])
            if (lane >= i + 1 && lane < n) {
                int r = lane;
                float s = Am[r][i + 1];
                for (int c = i + 2; c < n; c++) s += Am[r][c] * Am[c][i];
                pv[r] = taui * s;
            }
            __syncwarp();
            float vtp = pv[i + 1];
            for (int r = i + 2; r < n; r++) vtp += pv[r] * Am[r][i];
            float alph = -0.5f * taui * vtp;
            __syncwarp();
            if (lane >= i + 1 && lane < n) {
                if (lane == i + 1) pv[lane] += alph;
                else               pv[lane] += alph * Am[lane][i];
            }
            __syncwarp();
            if (lane >= i + 1 && lane < n) {
                int r = lane;
                float vr = (r == i + 1) ? 1.f : Am[r][i];
                float wr = pv[r];
                for (int c = i + 1; c < n; c++) {
                    float vc = (c == i + 1) ? 1.f : Am[c][i];
                    Am[r][c] -= vr * pv[c] + wr * vc;
                }
            }
            __syncwarp();
        }
        dd[i] = Am[i][i];
        tauv[i] = taui;
        __syncwarp();
    }
    dd[n - 1] = Am[n - 1][n - 1];

    // Z = I (row-owned)
    if (lane < n)
        for (int c = 0; c < n; c++) Zm[lane][c] = (lane == c) ? 1.f : 0.f;
    __syncwarp();

    // ---------------- ssteqr (compz='I'); Zm row-owned ----------------
    {
        const float eps = 5.9604645e-8f;
        const float eps2 = eps * eps;
        const float safmin = 1.17549435e-38f;
        const int nmaxit = n * 30;
        int jtot = 0;
        int l1 = 1;
#define Dv(i) dd[(i) - 1]
#define Ev(i) ee[(i) - 1]
        while (l1 <= n) {
            if (l1 > 1) Ev(l1 - 1) = 0.f;
            int m = n;
            if (l1 <= n - 1) {
                for (int mm = l1; mm <= n - 1; mm++) {
                    float tst = fabsf(Ev(mm));
                    if (tst == 0.f) { m = mm; break; }
                    if (tst <= fsqrta(fabsf(Dv(mm))) * fsqrta(fabsf(Dv(mm + 1))) * eps) {
                        Ev(mm) = 0.f; m = mm; break;
                    }
                }
            }
            int l = l1, lend = m;
            l1 = m + 1;
            if (lend == l) continue;
            float anorm = 0.f;
            for (int i = l; i <= lend; i++) anorm = fmaxf(anorm, fabsf(Dv(i)));
            for (int i = l; i <= lend - 1; i++) anorm = fmaxf(anorm, fabsf(Ev(i)));
            if (anorm == 0.f) continue;
            if (fabsf(Dv(lend)) < fabsf(Dv(l))) { int t = l; l = lend; lend = t; }

            if (lend > l) {
                // ---- QL iteration ----
                while (true) {
                    int m2 = lend;
                    if (l != lend) {
                        for (int mm = l; mm <= lend - 1; mm++) {
                            float tst = fabsf(Ev(mm)); tst = tst * tst;
                            if (tst <= (eps2 * fabsf(Dv(mm))) * fabsf(Dv(mm + 1)) + safmin) { m2 = mm; break; }
                        }
                    }
                    if (m2 < lend) Ev(m2) = 0.f;
                    float p = Dv(l);
                    if (m2 == l) {
                        Dv(l) = p; l++;
                        if (l <= lend) continue;
                        break;
                    }
                    if (m2 == l + 1) {
                        float rt1, rt2, cc, ss;
                        laev2f(Dv(l), Ev(l), Dv(l + 1), rt1, rt2, cc, ss);
                        if (lane < n) {
                            float t1 = Zm[lane][l];
                            float t0 = Zm[lane][l - 1];
                            Zm[lane][l] = cc * t1 - ss * t0;
                            Zm[lane][l - 1] = ss * t1 + cc * t0;
                        }
                        Dv(l) = rt1; Dv(l + 1) = rt2; Ev(l) = 0.f;
                        l += 2;
                        if (l <= lend) continue;
                        break;
                    }
                    if (jtot == nmaxit) break;
                    jtot++;
                    float g = fdivf(Dv(l + 1) - p, 2.f * Ev(l));
                    float r = lapy2f(g, 1.f);
                    g = Dv(m2) - p + fdivf(Ev(l), g + signf(r, g));
                    float s = 1.f, c = 1.f; p = 0.f;
                    for (int i = m2 - 1; i >= l; i--) {
                        float f = s * Ev(i), b = c * Ev(i);
                        lartgf(g, f, c, s, r);
                        if (i != m2 - 1) Ev(i + 1) = r;
                        g = Dv(i + 1) - p;
                        r = (Dv(i) - g) * s + 2.f * c * b;
                        p = s * r;
                        Dv(i + 1) = g + p;
                        g = c * r - b;
                        wcs[i - 1] = c;
                        wss[i - 1] = -s;                 // LAPACK stores -s for QL
                    }
                    if (lane < n) {
                        for (int j = m2 - l; j >= 1; j--) {
                            float ct = wcs[(l - 1) + (j - 1)], st = wss[(l - 1) + (j - 1)];
                            if (ct != 1.f || st != 0.f) {
                                int c1 = (l - 1) + j, c0 = c1 - 1;
                                float temp = Zm[lane][c1];
                                Zm[lane][c1] = ct * temp - st * Zm[lane][c0];
                                Zm[lane][c0] = st * temp + ct * Zm[lane][c0];
                            }
                        }
                    }
                    Dv(l) -= p;
                    Ev(l) = g;
                }
            } else {
                // ---- QR iteration ----
                while (true) {
                    int m2 = lend;
                    if (l != lend) {
                        for (int mm = l; mm >= lend + 1; mm--) {
                            float tst = fabsf(Ev(mm - 1)); tst = tst * tst;
                            if (tst <= (eps2 * fabsf(Dv(mm))) * fabsf(Dv(mm - 1)) + safmin) { m2 = mm; break; }
                        }
                    }
                    if (m2 > lend) Ev(m2 - 1) = 0.f;
                    float p = Dv(l);
                    if (m2 == l) {
                        Dv(l) = p; l--;
                        if (l >= lend) continue;
                        break;
                    }
                    if (m2 == l - 1) {
                        float rt1, rt2, cc, ss;
                        laev2f(Dv(l - 1), Ev(l - 1), Dv(l), rt1, rt2, cc, ss);
                        if (lane < n) {
                            float t1 = Zm[lane][l - 1];
                            float t0 = Zm[lane][l - 2];
                            Zm[lane][l - 1] = cc * t1 - ss * t0;
                            Zm[lane][l - 2] = ss * t1 + cc * t0;
                        }
                        Dv(l - 1) = rt1; Dv(l) = rt2; Ev(l - 1) = 0.f;
                        l -= 2;
                        if (l >= lend) continue;
                        break;
                    }
                    if (jtot == nmaxit) break;
                    jtot++;
                    float g = fdivf(Dv(l - 1) - p, 2.f * Ev(l - 1));
                    float r = lapy2f(g, 1.f);
                    g = Dv(m2) - p + fdivf(Ev(l - 1), g + signf(r, g));
                    float s = 1.f, c = 1.f; p = 0.f;
                    for (int i = m2; i <= l - 1; i++) {
                        float f = s * Ev(i), b = c * Ev(i);
                        lartgf(g, f, c, s, r);
                        if (i != m2) Ev(i - 1) = r;
                        g = Dv(i) - p;
                        r = (Dv(i + 1) - g) * s + 2.f * c * b;
                        p = s * r;
                        Dv(i) = g + p;
                        g = c * r - b;
                        wcs[i - 1] = c;
                        wss[i - 1] = s;
                    }
                    if (lane < n) {
                        for (int j = 1; j <= l - m2; j++) {
                            float ct = wcs[(m2 - 1) + (j - 1)], st = wss[(m2 - 1) + (j - 1)];
                            if (ct != 1.f || st != 0.f) {
                                int c1 = (m2 - 1) + j, c0 = c1 - 1;
                                float temp = Zm[lane][c1];
                                Zm[lane][c1] = ct * temp - st * Zm[lane][c0];
                                Zm[lane][c0] = st * temp + ct * Zm[lane][c0];
                            }
                        }
                    }
                    Dv(l) -= p;
                    Ev(l - 1) = g;
                }
            }
        }
        // selection sort ascending + column swaps (lane owns row)
        for (int ii = 2; ii <= n; ii++) {
            int i = ii - 1, k = i;
            float p = Dv(i);
            for (int j = ii; j <= n; j++)
                if (Dv(j) < p) { k = j; p = Dv(j); }
            if (k != i) {
                Dv(k) = Dv(i); Dv(i) = p;
                if (lane < n) {
                    float t = Zm[lane][i - 1];
                    Zm[lane][i - 1] = Zm[lane][k - 1];
                    Zm[lane][k - 1] = t;
                }
            }
        }
#undef Dv
#undef Ev
    }
    __syncwarp();   // Zm switches row-owned -> column-owned

    // ---------------- sormtr: Z := H(1)...H(n-1) Z ; lane owns column ----
    for (int i = n - 2; i >= 0; i--) {
        if (tauv[i] == 0.f) continue;
        if (lane < n) {
            int c = lane;
            float s = Zm[i + 1][c];
            for (int r = i + 2; r < n; r++) s += Am[r][i] * Zm[r][c];
            s *= tauv[i];
            Zm[i + 1][c] -= s;
            for (int r = i + 2; r < n; r++) Zm[r][c] -= s * Am[r][i];
        }
    }
    __syncwarp();   // back to row reads for the MLP

    // ---------------- MLP: relu(w @ W1^T + b1) @ W2^T + b2; 0.5*(sigmoid+1)
    if (lane < n) {
        float zr[DDIM];
#pragma unroll
        for (int k = 0; k < DDIM; k++) zr[k] = Zm[lane][k];
        float y2 = b2[0];
        for (int h = 0; h < HID; h++) {
            float a = b1[h];
#pragma unroll
            for (int k = 0; k < DDIM; k++) a += zr[k] * W1[h * DDIM + k];
            a = fmaxf(a, 0.f);
            y2 += a * W2[h];
        }
        out[lane] = 0.5f * (fdivf(1.f, 1.f + __expf(-y2)) + 1.f);
    }
}

// ---------------------------------------------------------------------------
extern "C" void kernel_launch(void* const* d_in, const int* in_sizes, int n_in,
                              void* d_out, int out_size) {
    const float* x  = (const float*)d_in[0];
    const float* W1 = (const float*)d_in[1];
    const float* b1 = (const float*)d_in[2];
    const float* W2 = (const float*)d_in[3];
    const float* b2 = (const float*)d_in[4];
    long long nrows = (long long)in_sizes[0] / DDIM;

    gram_kernel<<<GGRID, GTPB>>>(x, nrows);
    solve_kernel<<<1, GTPB>>>(W1, b1, W2, b2, (float*)d_out);
}